// round 5
// baseline (speedup 1.0000x reference)
#include <cuda_runtime.h>
#include <cstdint>

// Problem constants (fixed by the dataset)
#define M_MAX   8192
#define K_DIM   4096
#define N_DIM   4096
#define NBASIS  256

// Scratch (static device arrays — no allocation allowed)
__device__ int8_t g_x1[M_MAX * K_DIM];
__device__ int8_t g_x2[M_MAX * K_DIM];
__device__ float  g_sx[M_MAX];
__device__ int8_t g_b1[NBASIS * K_DIM];
__device__ int8_t g_b2[NBASIS * K_DIM];
__device__ float  g_sb[NBASIS];
__device__ int8_t g_w [N_DIM * K_DIM];
__device__ float  g_Pt[NBASIS * M_MAX];   // Pt[basis][m]

// ---------------------------------------------------------------------------
// Prep kernels
// ---------------------------------------------------------------------------

// Per-row dual int8 quantization: src_row ~= s*q1 + (s/127)*q2, s = max|row|/127
__global__ void quant_rows(const float* __restrict__ src,
                           int8_t* __restrict__ q1, int8_t* __restrict__ q2,
                           float* __restrict__ srow) {
    int row = blockIdx.x;
    const float4* s4 = (const float4*)(src + (size_t)row * K_DIM);
    float mx = 0.f;
    for (int i = threadIdx.x; i < K_DIM / 4; i += 256) {
        float4 v = s4[i];
        mx = fmaxf(mx, fmaxf(fmaxf(fabsf(v.x), fabsf(v.y)),
                             fmaxf(fabsf(v.z), fabsf(v.w))));
    }
    __shared__ float red[9];
    for (int o = 16; o; o >>= 1) mx = fmaxf(mx, __shfl_xor_sync(~0u, mx, o));
    if ((threadIdx.x & 31) == 0) red[threadIdx.x >> 5] = mx;
    __syncthreads();
    if (threadIdx.x == 0) {
        float v = red[0];
        for (int i = 1; i < 8; i++) v = fmaxf(v, red[i]);
        float s = fmaxf(v, 1e-20f) * (1.0f / 127.0f);
        red[8] = s;
        srow[row] = s;
    }
    __syncthreads();
    float s = red[8];
    float inv = 1.0f / s;
    float inv127 = inv * 127.0f;
    char4* o1 = (char4*)(q1 + (size_t)row * K_DIM);
    char4* o2 = (char4*)(q2 + (size_t)row * K_DIM);
    for (int i = threadIdx.x; i < K_DIM / 4; i += 256) {
        float4 v = s4[i];
        char4 a, b;
        int t;
        t = __float2int_rn(v.x * inv); a.x = (char)t;
        b.x = (char)__float2int_rn(fmaf(-s, (float)t, v.x) * inv127);
        t = __float2int_rn(v.y * inv); a.y = (char)t;
        b.y = (char)__float2int_rn(fmaf(-s, (float)t, v.y) * inv127);
        t = __float2int_rn(v.z * inv); a.z = (char)t;
        b.z = (char)__float2int_rn(fmaf(-s, (float)t, v.z) * inv127);
        t = __float2int_rn(v.w * inv); a.w = (char)t;
        b.w = (char)__float2int_rn(fmaf(-s, (float)t, v.w) * inv127);
        o1[i] = a;
        o2[i] = b;
    }
}

// w = q - 128 (exact int8)
__global__ void prep_w(const int* __restrict__ q, int8_t* __restrict__ w, int n4) {
    int i = blockIdx.x * blockDim.x + threadIdx.x;
    if (i >= n4) return;
    int4 v = ((const int4*)q)[i];
    char4 c;
    c.x = (char)(v.x - 128); c.y = (char)(v.y - 128);
    c.z = (char)(v.z - 128); c.w = (char)(v.w - 128);
    ((char4*)w)[i] = c;
}

// ---------------------------------------------------------------------------
// MMA helpers (sm_80-level: ldmatrix + mma.sync.m16n8k32.s8 + cp.async)
// ---------------------------------------------------------------------------

__device__ __forceinline__ void ldsm4(uint32_t& r0, uint32_t& r1,
                                      uint32_t& r2, uint32_t& r3, uint32_t a) {
    asm volatile("ldmatrix.sync.aligned.m8n8.x4.shared.b16 {%0,%1,%2,%3}, [%4];"
                 : "=r"(r0), "=r"(r1), "=r"(r2), "=r"(r3) : "r"(a));
}

__device__ __forceinline__ void mma8(int* c, const uint32_t* a, const uint32_t* b) {
    asm volatile(
        "mma.sync.aligned.m16n8k32.row.col.s32.s8.s8.s32 "
        "{%0,%1,%2,%3},{%4,%5,%6,%7},{%8,%9},{%0,%1,%2,%3};"
        : "+r"(c[0]), "+r"(c[1]), "+r"(c[2]), "+r"(c[3])
        : "r"(a[0]), "r"(a[1]), "r"(a[2]), "r"(a[3]), "r"(b[0]), "r"(b[1]));
}

__device__ __forceinline__ void cp16(uint32_t s, const void* g) {
    asm volatile("cp.async.cg.shared.global [%0], [%1], 16;" :: "r"(s), "l"(g));
}

#define ASTR 144   // 128B of K + 16B pad: conflict-free ldmatrix phases

// ---------------------------------------------------------------------------
// Big GEMM (int8): acc = X1[m] . W[o]  +  fused bitfield epilogue:
//   y[m][o] = sp[o]*sx[m]*acc + r[o]*Pt[idx[o]][m] + bias[o]
// CTA tile 128x256x128, 512 threads (4x4 warps, warp tile 32x64),
// 3-stage cp.async pipeline.
// ---------------------------------------------------------------------------

__global__ __launch_bounds__(512, 1)
void gemm_big(const int8_t* __restrict__ X, const int8_t* __restrict__ W,
              float* __restrict__ Y,
              const int* __restrict__ codes, const float* __restrict__ scales,
              const float* __restrict__ bias, const float* __restrict__ Pt,
              const float* __restrict__ sx, int N, int Mtot)
{
    constexpr int BM = 128, BN = 256, BK = 128;
    constexpr int STAGE = (BM + BN) * ASTR;     // 55296
    constexpr int OFF_ST = 4096;
    extern __shared__ char smem[];
    const int tid = threadIdx.x, lane = tid & 31, wid = tid >> 5;
    const int wm = wid & 3, wn = wid >> 2;
    const size_t mBase = (size_t)blockIdx.y * BM;
    const size_t nBase = (size_t)blockIdx.x * BN;
    const uint32_t sb = (uint32_t)__cvta_generic_to_shared(smem);

    // decode per-column params into smem
    int*   idx_s = (int*)smem;
    float* r_s   = (float*)smem + BN;
    float* sp_s  = (float*)smem + 2 * BN;
    float* b_s   = (float*)smem + 3 * BN;
    for (int c = tid; c < BN; c += 512) {
        int code = codes[nBase + c];
        idx_s[c] = code & 0xFF;
        r_s[c]   = (float)((code >> 8) & 0xFFFF) * (1.0f / 65535.0f);
        sp_s[c]  = scales[nBase + c] * (1.0f / 127.0f);
        b_s[c]   = bias[nBase + c];
    }

    int acc[2][8][4];
#pragma unroll
    for (int i = 0; i < 2; i++)
#pragma unroll
        for (int j = 0; j < 8; j++)
#pragma unroll
            for (int k = 0; k < 4; k++) acc[i][j][k] = 0;

    auto fill = [&](int s, int kt) {
        size_t koff = (size_t)kt * BK;
        uint32_t base = sb + OFF_ST + s * STAGE;
#pragma unroll
        for (int i = 0; i < 6; i++) {
            int id = tid + i * 512;
            bool isB = id >= BM * 8;
            int li = isB ? id - BM * 8 : id;
            int r = li >> 3, c = li & 7;
            const int8_t* src =
                (isB ? W + (nBase + r) * (size_t)K_DIM
                     : X + (mBase + r) * (size_t)K_DIM) + koff + c * 16;
            cp16(base + (isB ? BM * ASTR : 0) + r * ASTR + c * 16, src);
        }
        asm volatile("cp.async.commit_group;" ::: "memory");
    };

    fill(0, 0);
    fill(1, 1);
    const int KT = K_DIM / BK;   // 32
    const int lg = lane >> 3, li = lane & 7;

    for (int kt = 0; kt < KT; kt++) {
        int s = kt % 3;
        asm volatile("cp.async.wait_group 1;" ::: "memory");
        __syncthreads();
        if (kt + 2 < KT) fill((kt + 2) % 3, kt + 2);
        else asm volatile("cp.async.commit_group;" ::: "memory");

        uint32_t Ab = sb + OFF_ST + s * STAGE;
        uint32_t Bb = Ab + BM * ASTR;
#pragma unroll
        for (int k32 = 0; k32 < 4; k32++) {
            int kb = k32 * 32;
            uint32_t a[2][4], b[8][2];
#pragma unroll
            for (int mt = 0; mt < 2; mt++) {
                int row = wm * 32 + mt * 16 + li + (lg & 1) * 8;
                ldsm4(a[mt][0], a[mt][1], a[mt][2], a[mt][3],
                      Ab + row * ASTR + kb + (lg >> 1) * 16);
            }
#pragma unroll
            for (int g = 0; g < 4; g++) {
                int row = wn * 64 + g * 16 + li + (lg >> 1) * 8;
                uint32_t r0, r1, r2, r3;
                ldsm4(r0, r1, r2, r3, Bb + row * ASTR + kb + (lg & 1) * 16);
                b[2 * g][0] = r0; b[2 * g][1] = r1;
                b[2 * g + 1][0] = r2; b[2 * g + 1][1] = r3;
            }
#pragma unroll
            for (int mt = 0; mt < 2; mt++)
#pragma unroll
                for (int nt = 0; nt < 8; nt++)
                    mma8(acc[mt][nt], a[mt], b[nt]);
        }
    }
    asm volatile("cp.async.wait_group 0;" ::: "memory");
    __syncthreads();

    // Fused epilogue
    const int t4 = lane >> 2, t2 = (lane & 3) * 2;
#pragma unroll
    for (int mt = 0; mt < 2; mt++) {
#pragma unroll
        for (int p = 0; p < 2; p++) {
            size_t m = mBase + wm * 32 + mt * 16 + t4 + p * 8;
            float sxm = __ldg(&sx[m]);
#pragma unroll
            for (int nt = 0; nt < 8; nt++) {
                int nl = wn * 64 + nt * 8 + t2;
                size_t n = nBase + nl;
                float v0 = fmaf(sp_s[nl] * sxm, (float)acc[mt][nt][2 * p + 0],
                           fmaf(r_s[nl],
                                __ldg(&Pt[(size_t)idx_s[nl] * Mtot + m]), b_s[nl]));
                float v1 = fmaf(sp_s[nl + 1] * sxm, (float)acc[mt][nt][2 * p + 1],
                           fmaf(r_s[nl + 1],
                                __ldg(&Pt[(size_t)idx_s[nl + 1] * Mtot + m]), b_s[nl + 1]));
                *(float2*)(Y + m * (size_t)N + n) = make_float2(v0, v1);
            }
        }
    }
}

// ---------------------------------------------------------------------------
// P GEMM (dual int8, 3 passes): Pt[b][m] = sb[b]*sx[m]*(b1.x1 + (b1.x2 + b2.x1)/127)
// CTA tile 128x128x128, 256 threads (4x2 warps, warp tile 32x64).
// ---------------------------------------------------------------------------

#define P_STEP(ACC)                                                              \
    do {                                                                         \
        _Pragma("unroll")                                                        \
        for (int k32 = 0; k32 < 4; k32++) {                                      \
            int kb = k32 * 32;                                                   \
            uint32_t a[2][4], b[8][2];                                           \
            _Pragma("unroll")                                                    \
            for (int mt = 0; mt < 2; mt++) {                                     \
                int row = wm * 32 + mt * 16 + li + (lg & 1) * 8;                 \
                ldsm4(a[mt][0], a[mt][1], a[mt][2], a[mt][3],                    \
                      Ab + row * ASTR + kb + (lg >> 1) * 16);                    \
            }                                                                    \
            _Pragma("unroll")                                                    \
            for (int g = 0; g < 4; g++) {                                        \
                int row = wn * 64 + g * 16 + li + (lg >> 1) * 8;                 \
                uint32_t r0, r1, r2, r3;                                         \
                ldsm4(r0, r1, r2, r3, Bb + row * ASTR + kb + (lg & 1) * 16);     \
                b[2 * g][0] = r0; b[2 * g][1] = r1;                              \
                b[2 * g + 1][0] = r2; b[2 * g + 1][1] = r3;                      \
            }                                                                    \
            _Pragma("unroll")                                                    \
            for (int mt = 0; mt < 2; mt++)                                       \
                _Pragma("unroll")                                                \
                for (int nt = 0; nt < 8; nt++)                                   \
                    mma8(ACC[mt][nt], a[mt], b[nt]);                             \
        }                                                                        \
    } while (0)

__global__ __launch_bounds__(256, 1)
void gemm_P(const int8_t* __restrict__ B1, const int8_t* __restrict__ B2,
            const int8_t* __restrict__ X1, const int8_t* __restrict__ X2,
            const float* __restrict__ sbv, const float* __restrict__ sxv,
            float* __restrict__ Pt, int Mtot)
{
    constexpr int BM = 128, BN = 128, BK = 128;
    constexpr int STAGE = (BM + BN) * ASTR;     // 36864
    extern __shared__ char smem[];
    const int tid = threadIdx.x, lane = tid & 31, wid = tid >> 5;
    const int wm = wid & 3, wn = wid >> 2;      // 4 x 2 warps
    const size_t mBase = (size_t)blockIdx.y * BM;   // basis dim
    const size_t nBase = (size_t)blockIdx.x * BN;   // token dim
    const uint32_t sb = (uint32_t)__cvta_generic_to_shared(smem);

    int acc0[2][8][4], aux[2][8][4];
#pragma unroll
    for (int i = 0; i < 2; i++)
#pragma unroll
        for (int j = 0; j < 8; j++)
#pragma unroll
            for (int k = 0; k < 4; k++) { acc0[i][j][k] = 0; aux[i][j][k] = 0; }

    const int8_t* Ap[3] = {B1, B1, B2};
    const int8_t* Bp[3] = {X1, X2, X1};

    auto fill = [&](int s, int kt) {
        int pass = kt >> 5;
        const int8_t* A = Ap[pass];
        const int8_t* B = Bp[pass];
        size_t koff = (size_t)(kt & 31) * BK;
        uint32_t base = sb + s * STAGE;
#pragma unroll
        for (int i = 0; i < 8; i++) {
            int id = tid + i * 256;
            bool isB = id >= BM * 8;
            int li2 = isB ? id - BM * 8 : id;
            int r = li2 >> 3, c = li2 & 7;
            const int8_t* src =
                (isB ? B + (nBase + r) * (size_t)K_DIM
                     : A + (mBase + r) * (size_t)K_DIM) + koff + c * 16;
            cp16(base + (isB ? BM * ASTR : 0) + r * ASTR + c * 16, src);
        }
        asm volatile("cp.async.commit_group;" ::: "memory");
    };

    fill(0, 0);
    fill(1, 1);
    const int KT = 3 * (K_DIM / BK);   // 96
    const int lg = lane >> 3, li = lane & 7;

    for (int kt = 0; kt < KT; kt++) {
        int s = kt % 3;
        asm volatile("cp.async.wait_group 1;" ::: "memory");
        __syncthreads();
        if (kt + 2 < KT) fill((kt + 2) % 3, kt + 2);
        else asm volatile("cp.async.commit_group;" ::: "memory");

        uint32_t Ab = sb + s * STAGE;
        uint32_t Bb = Ab + BM * ASTR;
        if (kt < 32) P_STEP(acc0);
        else         P_STEP(aux);
    }
    asm volatile("cp.async.wait_group 0;" ::: "memory");
    __syncthreads();

    const int t4 = lane >> 2, t2 = (lane & 3) * 2;
#pragma unroll
    for (int mt = 0; mt < 2; mt++) {
#pragma unroll
        for (int p = 0; p < 2; p++) {
            size_t bg = mBase + wm * 32 + mt * 16 + t4 + p * 8;
            float sbb = __ldg(&sbv[bg]);
#pragma unroll
            for (int nt = 0; nt < 8; nt++) {
                int nl = wn * 64 + nt * 8 + t2;
                size_t mcol = nBase + nl;
                float s0 = sbb * __ldg(&sxv[mcol]);
                float s1 = sbb * __ldg(&sxv[mcol + 1]);
                float v0 = s0 * fmaf((float)aux[mt][nt][2 * p + 0], (1.0f / 127.0f),
                                     (float)acc0[mt][nt][2 * p + 0]);
                float v1 = s1 * fmaf((float)aux[mt][nt][2 * p + 1], (1.0f / 127.0f),
                                     (float)acc0[mt][nt][2 * p + 1]);
                *(float2*)(Pt + bg * (size_t)Mtot + mcol) = make_float2(v0, v1);
            }
        }
    }
}

// ---------------------------------------------------------------------------
// Launch
// ---------------------------------------------------------------------------

extern "C" void kernel_launch(void* const* d_in, const int* in_sizes, int n_in,
                              void* d_out, int out_size) {
    const float* x      = (const float*)d_in[0];
    const int*   codes  = (const int*)d_in[1];
    const float* basis  = (const float*)d_in[2];
    const int*   residq = (const int*)d_in[3];
    const float* scales = (const float*)d_in[4];
    const float* bias   = (const float*)d_in[5];
    float*       y      = (float*)d_out;

    int N = in_sizes[1];                 // 4096
    int K = in_sizes[2] / NBASIS;        // 4096
    int M = in_sizes[0] / K;             // 8192

    int8_t *x1, *x2, *b1, *b2, *w;
    float *sx, *sbv, *Pt;
    cudaGetSymbolAddress((void**)&x1,  g_x1);
    cudaGetSymbolAddress((void**)&x2,  g_x2);
    cudaGetSymbolAddress((void**)&sx,  g_sx);
    cudaGetSymbolAddress((void**)&b1,  g_b1);
    cudaGetSymbolAddress((void**)&b2,  g_b2);
    cudaGetSymbolAddress((void**)&sbv, g_sb);
    cudaGetSymbolAddress((void**)&w,   g_w);
    cudaGetSymbolAddress((void**)&Pt,  g_Pt);

    constexpr int SMEM_BIG = 4096 + 3 * (128 + 256) * ASTR;  // 169984
    constexpr int SMEM_P   = 3 * (128 + 128) * ASTR;         // 110592
    static bool attr_done = false;
    cudaFuncSetAttribute(gemm_big, cudaFuncAttributeMaxDynamicSharedMemorySize, SMEM_BIG);
    cudaFuncSetAttribute(gemm_P,   cudaFuncAttributeMaxDynamicSharedMemorySize, SMEM_P);
    (void)attr_done;

    // 1) Preprocess: dual-int8 x and basis, exact int8 residual weights
    quant_rows<<<M, 256>>>(x, x1, x2, sx);
    quant_rows<<<NBASIS, 256>>>(basis, b1, b2, sbv);
    int nw4 = (N * K) / 4;
    prep_w<<<(nw4 + 255) / 256, 256>>>(residq, w, nw4);

    // 2) P GEMM (transposed): Pt[b][m] = sb[b]*sx[m]*(b1.x1 + (b1.x2 + b2.x1)/127)
    gemm_P<<<dim3(M / 128, NBASIS / 128), 256, SMEM_P>>>(
        b1, b2, x1, x2, sbv, sx, Pt, M);

    // 3) Big GEMM + fused bitfield epilogue:
    //    y[m][o] = (scales[o]/127)*sx[m]*(x1.w) + r[o]*Pt[idx[o]][m] + bias[o]
    gemm_big<<<dim3(N / 256, M / 128), 512, SMEM_BIG>>>(
        x1, w, y, codes, scales, bias, Pt, sx, N, M);
}

// round 7
// speedup vs baseline: 2.3697x; 2.3697x over previous
#include <cuda_runtime.h>
#include <cuda_bf16.h>
#include <cstdint>

// Problem constants (fixed by the dataset)
#define M_MAX   8192
#define K_DIM   4096
#define N_DIM   4096
#define NBASIS  256

// Scratch (static device arrays — no allocation allowed)
__device__ __nv_bfloat16 g_Xhi[M_MAX * K_DIM];
__device__ __nv_bfloat16 g_Xlo[M_MAX * K_DIM];
__device__ __nv_bfloat16 g_Wres[N_DIM * K_DIM];
__device__ __nv_bfloat16 g_Bhi[NBASIS * K_DIM];
__device__ __nv_bfloat16 g_Blo[NBASIS * K_DIM];
__device__ float         g_Pt[NBASIS * M_MAX];   // Pt[basis][m]

// ---------------------------------------------------------------------------
// Prep kernels
// ---------------------------------------------------------------------------

__global__ void prep_x(const float* __restrict__ x,
                       __nv_bfloat16* __restrict__ hi,
                       __nv_bfloat16* __restrict__ lo, int n4) {
    int i = blockIdx.x * blockDim.x + threadIdx.x;
    if (i >= n4) return;
    float4 v = ((const float4*)x)[i];
    __nv_bfloat162 h01 = __floats2bfloat162_rn(v.x, v.y);
    __nv_bfloat162 h23 = __floats2bfloat162_rn(v.z, v.w);
    ((__nv_bfloat162*)hi)[2 * i]     = h01;
    ((__nv_bfloat162*)hi)[2 * i + 1] = h23;
    float l0 = v.x - __bfloat162float(h01.x);
    float l1 = v.y - __bfloat162float(h01.y);
    float l2 = v.z - __bfloat162float(h23.x);
    float l3 = v.w - __bfloat162float(h23.y);
    ((__nv_bfloat162*)lo)[2 * i]     = __floats2bfloat162_rn(l0, l1);
    ((__nv_bfloat162*)lo)[2 * i + 1] = __floats2bfloat162_rn(l2, l3);
}

__global__ void prep_w(const int* __restrict__ q,
                       __nv_bfloat16* __restrict__ w, int n4) {
    int i = blockIdx.x * blockDim.x + threadIdx.x;
    if (i >= n4) return;
    int4 v = ((const int4*)q)[i];
    // q - 128 is an integer in [-128,127]: exactly representable in bf16.
    __nv_bfloat162 w01 = __floats2bfloat162_rn((float)(v.x - 128), (float)(v.y - 128));
    __nv_bfloat162 w23 = __floats2bfloat162_rn((float)(v.z - 128), (float)(v.w - 128));
    ((__nv_bfloat162*)w)[2 * i]     = w01;
    ((__nv_bfloat162*)w)[2 * i + 1] = w23;
}

// ---------------------------------------------------------------------------
// MMA helpers (legacy HMMA pipe: ldmatrix + mma.sync.m16n8k16.bf16 + cp.async)
// ---------------------------------------------------------------------------

__device__ __forceinline__ void ldsm4(uint32_t& r0, uint32_t& r1,
                                      uint32_t& r2, uint32_t& r3, uint32_t a) {
    asm volatile("ldmatrix.sync.aligned.m8n8.x4.shared.b16 {%0,%1,%2,%3}, [%4];"
                 : "=r"(r0), "=r"(r1), "=r"(r2), "=r"(r3) : "r"(a));
}

__device__ __forceinline__ void mma16(float* c, const uint32_t* a, const uint32_t* b) {
    asm volatile(
        "mma.sync.aligned.m16n8k16.row.col.f32.bf16.bf16.f32 "
        "{%0,%1,%2,%3},{%4,%5,%6,%7},{%8,%9},{%0,%1,%2,%3};"
        : "+f"(c[0]), "+f"(c[1]), "+f"(c[2]), "+f"(c[3])
        : "r"(a[0]), "r"(a[1]), "r"(a[2]), "r"(a[3]), "r"(b[0]), "r"(b[1]));
}

__device__ __forceinline__ void cp16(uint32_t s, const void* g) {
    asm volatile("cp.async.cg.shared.global [%0], [%1], 16;" :: "r"(s), "l"(g));
}

#define ASTR 144   // 128B of K (64 bf16) + 16B pad: conflict-free ldmatrix phases

// ---------------------------------------------------------------------------
// Big GEMM (bf16): acc = Xhi[m] . Wres[o]  +  fused bitfield epilogue:
//   y[m][o] = sp[o]*acc + r[o]*Pt[idx[o]][m] + bias[o]
// CTA tile 128x256x64(elems), 512 threads (4x4 warps, warp tile 32x64),
// 3-stage cp.async pipeline.
// ---------------------------------------------------------------------------

__global__ __launch_bounds__(512, 1)
void gemm_big(const __nv_bfloat16* __restrict__ X, const __nv_bfloat16* __restrict__ W,
              float* __restrict__ Y,
              const int* __restrict__ codes, const float* __restrict__ scales,
              const float* __restrict__ bias, const float* __restrict__ Pt,
              int N, int Mtot)
{
    constexpr int BM = 128, BN = 256;            // rows; row = 64 bf16 = 128B
    constexpr int STAGE = (BM + BN) * ASTR;      // 55296
    constexpr int OFF_ST = 4096;
    extern __shared__ char smem[];
    const int tid = threadIdx.x, lane = tid & 31, wid = tid >> 5;
    const int wm = wid & 3, wn = wid >> 2;
    const size_t mBase = (size_t)blockIdx.y * BM;
    const size_t nBase = (size_t)blockIdx.x * BN;
    const uint32_t sb = (uint32_t)__cvta_generic_to_shared(smem);

    // decode per-column params into smem
    int*   idx_s = (int*)smem;
    float* r_s   = (float*)smem + BN;
    float* sp_s  = (float*)smem + 2 * BN;
    float* b_s   = (float*)smem + 3 * BN;
    for (int c = tid; c < BN; c += 512) {
        int code = codes[nBase + c];
        idx_s[c] = code & 0xFF;
        r_s[c]   = (float)((code >> 8) & 0xFFFF) * (1.0f / 65535.0f);
        sp_s[c]  = scales[nBase + c] * (1.0f / 127.0f);
        b_s[c]   = bias[nBase + c];
    }

    float acc[2][8][4];
#pragma unroll
    for (int i = 0; i < 2; i++)
#pragma unroll
        for (int j = 0; j < 8; j++)
#pragma unroll
            for (int k = 0; k < 4; k++) acc[i][j][k] = 0.f;

    auto fill = [&](int s, int kt) {
        size_t koff = (size_t)kt * 64;           // elements
        uint32_t base = sb + OFF_ST + s * STAGE;
#pragma unroll
        for (int i = 0; i < 6; i++) {
            int id = tid + i * 512;
            bool isB = id >= BM * 8;
            int li = isB ? id - BM * 8 : id;
            int r = li >> 3, c = li & 7;
            const __nv_bfloat16* src =
                (isB ? W + (nBase + r) * (size_t)K_DIM
                     : X + (mBase + r) * (size_t)K_DIM) + koff + c * 8;
            cp16(base + (isB ? BM * ASTR : 0) + r * ASTR + c * 16, src);
        }
        asm volatile("cp.async.commit_group;" ::: "memory");
    };

    fill(0, 0);
    fill(1, 1);
    const int KT = K_DIM / 64;   // 64
    const int lg = lane >> 3, li = lane & 7;

    for (int kt = 0; kt < KT; kt++) {
        int s = kt % 3;
        asm volatile("cp.async.wait_group 1;" ::: "memory");
        __syncthreads();
        if (kt + 2 < KT) fill((kt + 2) % 3, kt + 2);
        else asm volatile("cp.async.commit_group;" ::: "memory");

        uint32_t Ab = sb + OFF_ST + s * STAGE;
        uint32_t Bb = Ab + BM * ASTR;
#pragma unroll
        for (int k16 = 0; k16 < 4; k16++) {
            int kb = k16 * 32;                   // bytes (16 bf16)
            uint32_t a[2][4], b[8][2];
#pragma unroll
            for (int mt = 0; mt < 2; mt++) {
                int row = wm * 32 + mt * 16 + li + (lg & 1) * 8;
                ldsm4(a[mt][0], a[mt][1], a[mt][2], a[mt][3],
                      Ab + row * ASTR + kb + (lg >> 1) * 16);
            }
#pragma unroll
            for (int g = 0; g < 4; g++) {
                int row = wn * 64 + g * 16 + li + (lg >> 1) * 8;
                uint32_t r0, r1, r2, r3;
                ldsm4(r0, r1, r2, r3, Bb + row * ASTR + kb + (lg & 1) * 16);
                b[2 * g][0] = r0; b[2 * g][1] = r1;
                b[2 * g + 1][0] = r2; b[2 * g + 1][1] = r3;
            }
#pragma unroll
            for (int mt = 0; mt < 2; mt++)
#pragma unroll
                for (int nt = 0; nt < 8; nt++)
                    mma16(acc[mt][nt], a[mt], b[nt]);
        }
    }
    asm volatile("cp.async.wait_group 0;" ::: "memory");
    __syncthreads();

    // Fused epilogue
    const int t4 = lane >> 2, t2 = (lane & 3) * 2;
#pragma unroll
    for (int mt = 0; mt < 2; mt++) {
#pragma unroll
        for (int p = 0; p < 2; p++) {
            size_t m = mBase + wm * 32 + mt * 16 + t4 + p * 8;
#pragma unroll
            for (int nt = 0; nt < 8; nt++) {
                int nl = wn * 64 + nt * 8 + t2;
                size_t n = nBase + nl;
                float v0 = fmaf(sp_s[nl], acc[mt][nt][2 * p + 0],
                           fmaf(r_s[nl],
                                __ldg(&Pt[(size_t)idx_s[nl] * Mtot + m]), b_s[nl]));
                float v1 = fmaf(sp_s[nl + 1], acc[mt][nt][2 * p + 1],
                           fmaf(r_s[nl + 1],
                                __ldg(&Pt[(size_t)idx_s[nl + 1] * Mtot + m]), b_s[nl + 1]));
                *(float2*)(Y + m * (size_t)N + n) = make_float2(v0, v1);
            }
        }
    }
}

// ---------------------------------------------------------------------------
// P GEMM (bf16, 3 passes into one fp32 accumulator):
//   Pt[b][m] = Bhi[b].Xhi[m] + Blo[b].Xhi[m] + Bhi[b].Xlo[m]
// CTA tile 128x128x64, 512 threads (4x4 warps, warp tile 32x32).
// ---------------------------------------------------------------------------

__global__ __launch_bounds__(512, 1)
void gemm_P(const __nv_bfloat16* __restrict__ Bhi, const __nv_bfloat16* __restrict__ Blo,
            const __nv_bfloat16* __restrict__ Xhi, const __nv_bfloat16* __restrict__ Xlo,
            float* __restrict__ Pt, int Mtot)
{
    constexpr int BM = 128, BN = 128;
    constexpr int STAGE = (BM + BN) * ASTR;      // 36864
    extern __shared__ char smem[];
    const int tid = threadIdx.x, lane = tid & 31, wid = tid >> 5;
    const int wm = wid & 3, wn = wid >> 2;       // 4 x 4 warps, warp tile 32x32
    const size_t mBase = (size_t)blockIdx.y * BM;    // basis dim
    const size_t nBase = (size_t)blockIdx.x * BN;    // token dim
    const uint32_t sb = (uint32_t)__cvta_generic_to_shared(smem);

    float acc[2][4][4];
#pragma unroll
    for (int i = 0; i < 2; i++)
#pragma unroll
        for (int j = 0; j < 4; j++)
#pragma unroll
            for (int k = 0; k < 4; k++) acc[i][j][k] = 0.f;

    const __nv_bfloat16* Ap[3] = {Bhi, Blo, Bhi};
    const __nv_bfloat16* Bp[3] = {Xhi, Xhi, Xlo};

    auto fill = [&](int s, int kt) {
        int pass = kt >> 6;                      // 64 k-steps per pass
        const __nv_bfloat16* A = Ap[pass];
        const __nv_bfloat16* B = Bp[pass];
        size_t koff = (size_t)(kt & 63) * 64;
        uint32_t base = sb + s * STAGE;
#pragma unroll
        for (int i = 0; i < 4; i++) {
            int id = tid + i * 512;
            bool isB = id >= BM * 8;
            int li2 = isB ? id - BM * 8 : id;
            int r = li2 >> 3, c = li2 & 7;
            const __nv_bfloat16* src =
                (isB ? B + (nBase + r) * (size_t)K_DIM
                     : A + (mBase + r) * (size_t)K_DIM) + koff + c * 8;
            cp16(base + (isB ? BM * ASTR : 0) + r * ASTR + c * 16, src);
        }
        asm volatile("cp.async.commit_group;" ::: "memory");
    };

    fill(0, 0);
    fill(1, 1);
    const int KT = 3 * (K_DIM / 64);   // 192
    const int lg = lane >> 3, li = lane & 7;

    for (int kt = 0; kt < KT; kt++) {
        int s = kt % 3;
        asm volatile("cp.async.wait_group 1;" ::: "memory");
        __syncthreads();
        if (kt + 2 < KT) fill((kt + 2) % 3, kt + 2);
        else asm volatile("cp.async.commit_group;" ::: "memory");

        uint32_t Ab = sb + s * STAGE;
        uint32_t Bb = Ab + BM * ASTR;
#pragma unroll
        for (int k16 = 0; k16 < 4; k16++) {
            int kb = k16 * 32;
            uint32_t a[2][4], b[4][2];
#pragma unroll
            for (int mt = 0; mt < 2; mt++) {
                int row = wm * 32 + mt * 16 + li + (lg & 1) * 8;
                ldsm4(a[mt][0], a[mt][1], a[mt][2], a[mt][3],
                      Ab + row * ASTR + kb + (lg >> 1) * 16);
            }
#pragma unroll
            for (int g = 0; g < 2; g++) {
                int row = wn * 32 + g * 16 + li + (lg >> 1) * 8;
                uint32_t r0, r1, r2, r3;
                ldsm4(r0, r1, r2, r3, Bb + row * ASTR + kb + (lg & 1) * 16);
                b[2 * g][0] = r0; b[2 * g][1] = r1;
                b[2 * g + 1][0] = r2; b[2 * g + 1][1] = r3;
            }
#pragma unroll
            for (int mt = 0; mt < 2; mt++)
#pragma unroll
                for (int nt = 0; nt < 4; nt++)
                    mma16(acc[mt][nt], a[mt], b[nt]);
        }
    }
    asm volatile("cp.async.wait_group 0;" ::: "memory");
    __syncthreads();

    const int t4 = lane >> 2, t2 = (lane & 3) * 2;
#pragma unroll
    for (int mt = 0; mt < 2; mt++) {
#pragma unroll
        for (int p = 0; p < 2; p++) {
            size_t bg = mBase + wm * 32 + mt * 16 + t4 + p * 8;
#pragma unroll
            for (int nt = 0; nt < 4; nt++) {
                size_t mcol = nBase + wn * 32 + nt * 8 + t2;
                *(float2*)(Pt + bg * (size_t)Mtot + mcol) =
                    make_float2(acc[mt][nt][2 * p + 0], acc[mt][nt][2 * p + 1]);
            }
        }
    }
}

// ---------------------------------------------------------------------------
// Launch
// ---------------------------------------------------------------------------

extern "C" void kernel_launch(void* const* d_in, const int* in_sizes, int n_in,
                              void* d_out, int out_size) {
    const float* x      = (const float*)d_in[0];
    const int*   codes  = (const int*)d_in[1];
    const float* basis  = (const float*)d_in[2];
    const int*   residq = (const int*)d_in[3];
    const float* scales = (const float*)d_in[4];
    const float* bias   = (const float*)d_in[5];
    float*       y      = (float*)d_out;

    int N = in_sizes[1];                 // 4096
    int K = in_sizes[2] / NBASIS;        // 4096
    int M = in_sizes[0] / K;             // 8192

    __nv_bfloat16 *Xhi, *Xlo, *Wres, *Bhi, *Blo;
    float* Pt;
    cudaGetSymbolAddress((void**)&Xhi,  g_Xhi);
    cudaGetSymbolAddress((void**)&Xlo,  g_Xlo);
    cudaGetSymbolAddress((void**)&Wres, g_Wres);
    cudaGetSymbolAddress((void**)&Bhi,  g_Bhi);
    cudaGetSymbolAddress((void**)&Blo,  g_Blo);
    cudaGetSymbolAddress((void**)&Pt,   g_Pt);

    constexpr int SMEM_BIG = 4096 + 3 * (128 + 256) * ASTR;  // 169984
    constexpr int SMEM_P   = 3 * (128 + 128) * ASTR;         // 110592
    cudaFuncSetAttribute(gemm_big, cudaFuncAttributeMaxDynamicSharedMemorySize, SMEM_BIG);
    cudaFuncSetAttribute(gemm_P,   cudaFuncAttributeMaxDynamicSharedMemorySize, SMEM_P);

    // 1) Preprocess: split x and basis into bf16 hi/lo; residual -> exact bf16 ints
    int nx4 = (M * K) / 4;
    prep_x<<<(nx4 + 255) / 256, 256>>>(x, Xhi, Xlo, nx4);
    int nb4 = (NBASIS * K) / 4;
    prep_x<<<(nb4 + 255) / 256, 256>>>(basis, Bhi, Blo, nb4);
    int nw4 = (N * K) / 4;
    prep_w<<<(nw4 + 255) / 256, 256>>>(residq, Wres, nw4);

    // 2) P GEMM (transposed): Pt[b][m] = Bhi.Xhi + Blo.Xhi + Bhi.Xlo
    gemm_P<<<dim3(M / 128, NBASIS / 128), 512, SMEM_P>>>(
        Bhi, Blo, Xhi, Xlo, Pt, M);

    // 3) Big GEMM + fused bitfield epilogue:
    //    y[m][o] = (scales[o]/127)*(Xhi.Wres[o]) + r[o]*Pt[idx[o]][m] + bias[o]
    gemm_big<<<dim3(N / 256, M / 128), 512, SMEM_BIG>>>(
        Xhi, Wres, y, codes, scales, bias, Pt, N, M);
}